// round 5
// baseline (speedup 1.0000x reference)
#include <cuda_runtime.h>
#include <math.h>

// Problem shape is fixed: N = 16384.
#define N_ELEM  16384
#define TN      128                         // tile dimension (rows=cols=threads)
#define NTILES  (N_ELEM / TN)               // 128
#define NBLOCKS (NTILES * (NTILES + 1) / 2) // 8256 upper-triangle tiles

// Scratch for deterministic two-stage reduction (no cudaMalloc allowed).
__device__ float g_partials[NBLOCKS];

__device__ __forceinline__ float ex2f(float x) {
    float y; asm("ex2.approx.f32 %0, %1;" : "=f"(y) : "f"(x)); return y;
}
__device__ __forceinline__ float rcpf(float x) {
    float y; asm("rcp.approx.f32 %0, %1;" : "=f"(y) : "f"(x)); return y;
}

// One block = one TN x TN tile (I,J) of the upper triangle (I <= J).
// Computes  sum_{i in tile I, j in tile J} sigmoid(p_i * p_j) * |t_i - t_j|.
// Diagonal tiles (I==J) are computed full and scaled by 0.5: the diagonal
// itself contributes 0 (|t_i - t_i| = 0) and the tile is symmetric.
__global__ __launch_bounds__(TN) void pair_tile_kernel(
    const float* __restrict__ yt, const float* __restrict__ yp)
{
    __shared__ float ts[TN];
    __shared__ float qs[TN];
    __shared__ float red[TN];

    // Invert linear triangular block index k -> (I, J), I <= J.
    // offset(I) = I*NTILES - I*(I-1)/2
    const int k = blockIdx.x;
    const float disc = 2.0f * (float)NTILES + 1.0f;
    int I = (int)((disc - sqrtf(disc * disc - 8.0f * (float)k)) * 0.5f);
    if (I < 0) I = 0;
    if (I >= NTILES) I = NTILES - 1;
    while (((I + 1) * NTILES - ((I + 1) * I) / 2) <= k) ++I;
    while ((I * NTILES - (I * (I - 1)) / 2) > k) --I;
    const int J = I + (k - (I * NTILES - (I * (I - 1)) / 2));

    const int tid = threadIdx.x;

    // Stage column tile: t_j and q_j = -log2(e) * p_j  (so ex2(p_i*q_j) = exp(-p_i*p_j)).
    const int jg = J * TN + tid;
    ts[tid] = yt[jg];
    qs[tid] = yp[jg] * (-1.4426950408889634f);

    // This thread's row.
    const int ig = I * TN + tid;
    const float pi = yp[ig];
    const float ti = yt[ig];
    __syncthreads();

    // 4 independent accumulator chains for MUFU/FMA latency hiding.
    float a0 = 0.f, a1 = 0.f, a2 = 0.f, a3 = 0.f;
    #pragma unroll 8
    for (int j = 0; j < TN; j += 4) {
        const float e0 = ex2f(pi * qs[j + 0]);
        const float e1 = ex2f(pi * qs[j + 1]);
        const float e2 = ex2f(pi * qs[j + 2]);
        const float e3 = ex2f(pi * qs[j + 3]);
        const float s0 = rcpf(1.0f + e0);
        const float s1 = rcpf(1.0f + e1);
        const float s2 = rcpf(1.0f + e2);
        const float s3 = rcpf(1.0f + e3);
        a0 += s0 * fabsf(ti - ts[j + 0]);
        a1 += s1 * fabsf(ti - ts[j + 1]);
        a2 += s2 * fabsf(ti - ts[j + 2]);
        a3 += s3 * fabsf(ti - ts[j + 3]);
    }

    red[tid] = (a0 + a1) + (a2 + a3);
    __syncthreads();
    #pragma unroll
    for (int s = TN / 2; s > 0; s >>= 1) {
        if (tid < s) red[tid] += red[tid + s];
        __syncthreads();
    }
    if (tid == 0) {
        g_partials[k] = (I == J) ? 0.5f * red[0] : red[0];
    }
}

// Deterministic final reduction in double; writes -S / N^2.
__global__ void reduce_kernel(float* __restrict__ out)
{
    __shared__ double sred[256];
    const int tid = threadIdx.x;
    double s = 0.0;
    for (int i = tid; i < NBLOCKS; i += 256) s += (double)g_partials[i];
    sred[tid] = s;
    __syncthreads();
    #pragma unroll
    for (int w = 128; w > 0; w >>= 1) {
        if (tid < w) sred[tid] += sred[tid + w];
        __syncthreads();
    }
    if (tid == 0) {
        const double n2 = (double)N_ELEM * (double)N_ELEM;
        out[0] = (float)(-sred[0] / n2);
    }
}

extern "C" void kernel_launch(void* const* d_in, const int* in_sizes, int n_in,
                              void* d_out, int out_size)
{
    const float* yt = (const float*)d_in[0];  // y_true
    const float* yp = (const float*)d_in[1];  // y_pred
    float* out = (float*)d_out;

    pair_tile_kernel<<<NBLOCKS, TN>>>(yt, yp);
    reduce_kernel<<<1, 256>>>(out);
}

// round 6
// speedup vs baseline: 1.5560x; 1.5560x over previous
#include <cuda_runtime.h>
#include <math.h>

// Problem shape is fixed: N = 16384.
#define N_ELEM  16384
#define TN      128                         // tile dimension (rows=cols=threads)
#define NTILES  (N_ELEM / TN)               // 128
#define NBLOCKS (NTILES * (NTILES + 1) / 2) // 8256 upper-triangle tiles

typedef unsigned long long ull;

// Scratch for deterministic two-stage reduction (no cudaMalloc allowed).
__device__ float        g_partials[NBLOCKS];
__device__ unsigned int g_arrive = 0;       // reset to 0 by last block each launch

__device__ __forceinline__ float tanhf_mufu(float x) {
    float y; asm("tanh.approx.f32 %0, %1;" : "=f"(y) : "f"(x)); return y;
}
__device__ __forceinline__ ull pack2(float lo, float hi) {
    ull r; asm("mov.b64 %0, {%1, %2};" : "=l"(r) : "f"(lo), "f"(hi)); return r;
}
__device__ __forceinline__ void unpack2(float& lo, float& hi, ull v) {
    asm("mov.b64 {%0, %1}, %2;" : "=f"(lo), "=f"(hi) : "l"(v));
}
__device__ __forceinline__ ull add2(ull a, ull b) {
    ull r; asm("add.rn.f32x2 %0, %1, %2;" : "=l"(r) : "l"(a), "l"(b)); return r;
}
__device__ __forceinline__ ull mul2(ull a, ull b) {
    ull r; asm("mul.rn.f32x2 %0, %1, %2;" : "=l"(r) : "l"(a), "l"(b)); return r;
}
__device__ __forceinline__ ull fma2(ull a, ull b, ull c) {
    ull r; asm("fma.rn.f32x2 %0, %1, %2, %3;" : "=l"(r) : "l"(a), "l"(b), "l"(c)); return r;
}

// One block = one TN x TN tile (I,J) of the upper triangle (I <= J).
// sigmoid(z) = 0.5 + 0.5*tanh(z/2) =>
//   sum_tile sigmoid(p_i p_j)*|t_i - t_j| = 0.5*(A + B),
//   A = sum tanh(p_i * (p_j/2)) * |d|,  B = sum |d|.
// Diagonal tiles computed full and scaled 0.5 (diag itself contributes 0).
__global__ __launch_bounds__(TN) void pair_tile_kernel(
    const float* __restrict__ yt, const float* __restrict__ yp,
    float* __restrict__ out)
{
    // sh[m].x = packed (-t(2m), -t(2m+1)); sh[m].y = packed (p(2m)/2, p(2m+1)/2)
    __shared__ __align__(16) ulonglong2 sh[TN / 2];
    __shared__ float  red[TN];
    __shared__ double dred[TN];
    __shared__ unsigned int is_last;

    // Invert linear triangular block index k -> (I, J), I <= J.
    const int k = blockIdx.x;
    const float disc = 2.0f * (float)NTILES + 1.0f;
    int I = (int)((disc - sqrtf(disc * disc - 8.0f * (float)k)) * 0.5f);
    if (I < 0) I = 0;
    if (I >= NTILES) I = NTILES - 1;
    while (((I + 1) * NTILES - ((I + 1) * I) / 2) <= k) ++I;
    while ((I * NTILES - (I * (I - 1)) / 2) > k) --I;
    const int J = I + (k - (I * NTILES - (I * (I - 1)) / 2));

    const int tid = threadIdx.x;

    // Stage column tile (interleaved packed layout for LDS.128 broadcast reads).
    {
        const int jg = J * TN + tid;
        const float tj = yt[jg];
        const float pj = yp[jg];
        float* sf = (float*)sh;
        const int m = tid >> 1, l = tid & 1;
        sf[4 * m + l]     = -tj;
        sf[4 * m + 2 + l] = 0.5f * pj;
    }

    // This thread's row.
    const int ig = I * TN + tid;
    const float pi = yp[ig];
    const float ti = yt[ig];
    const ull tip = pack2(ti, ti);
    const ull pip = pack2(pi, pi);
    __syncthreads();

    // Packed accumulators: A (tanh-weighted), B (plain |d|), 2 chains each.
    ull A0 = 0ull, A1 = 0ull, B0 = 0ull, B1 = 0ull;
    #pragma unroll 8
    for (int m = 0; m < TN / 2; m += 2) {
        const ulonglong2 v0 = sh[m];
        const ulonglong2 v1 = sh[m + 1];
        const ull d0  = add2(tip, v0.x);                  // (ti - t, ti - t')
        const ull d1  = add2(tip, v1.x);
        const ull ad0 = d0 & 0x7FFFFFFF7FFFFFFFull;       // |d| both lanes (ALU)
        const ull ad1 = d1 & 0x7FFFFFFF7FFFFFFFull;
        const ull x0  = mul2(pip, v0.y);                  // pi * p_j/2
        const ull x1  = mul2(pip, v1.y);
        float xa, xb, xc, xd;
        unpack2(xa, xb, x0);
        unpack2(xc, xd, x1);
        const ull th0 = pack2(tanhf_mufu(xa), tanhf_mufu(xb));
        const ull th1 = pack2(tanhf_mufu(xc), tanhf_mufu(xd));
        A0 = fma2(th0, ad0, A0);
        A1 = fma2(th1, ad1, A1);
        B0 = add2(B0, ad0);
        B1 = add2(B1, ad1);
    }

    float a0l, a0h, a1l, a1h, b0l, b0h, b1l, b1h;
    unpack2(a0l, a0h, A0); unpack2(a1l, a1h, A1);
    unpack2(b0l, b0h, B0); unpack2(b1l, b1h, B1);
    float P = 0.5f * (((a0l + a0h) + (a1l + a1h)) + ((b0l + b0h) + (b1l + b1h)));
    if (I == J) P *= 0.5f;

    // Block reduction (shared tree).
    red[tid] = P;
    __syncthreads();
    #pragma unroll
    for (int s = TN / 2; s > 0; s >>= 1) {
        if (tid < s) red[tid] += red[tid + s];
        __syncthreads();
    }

    // Publish partial; last-arriving block does the (deterministic) final sum.
    if (tid == 0) {
        g_partials[k] = red[0];
        __threadfence();
        unsigned int old = atomicAdd(&g_arrive, 1u);
        is_last = (old == (unsigned)(NBLOCKS - 1)) ? 1u : 0u;
    }
    __syncthreads();

    if (is_last) {
        __threadfence();
        double s = 0.0;
        for (int i = tid; i < NBLOCKS; i += TN)  // fixed order -> deterministic
            s += (double)g_partials[i];
        dred[tid] = s;
        __syncthreads();
        #pragma unroll
        for (int w = TN / 2; w > 0; w >>= 1) {
            if (tid < w) dred[tid] += dred[tid + w];
            __syncthreads();
        }
        if (tid == 0) {
            const double n2 = (double)N_ELEM * (double)N_ELEM;
            out[0] = (float)(-dred[0] / n2);
            g_arrive = 0;  // re-arm for next graph replay
        }
    }
}

extern "C" void kernel_launch(void* const* d_in, const int* in_sizes, int n_in,
                              void* d_out, int out_size)
{
    const float* yt = (const float*)d_in[0];  // y_true
    const float* yp = (const float*)d_in[1];  // y_pred
    float* out = (float*)d_out;

    pair_tile_kernel<<<NBLOCKS, TN>>>(yt, yp, out);
}

// round 7
// speedup vs baseline: 1.7279x; 1.1105x over previous
#include <cuda_runtime.h>
#include <math.h>

// Problem shape is fixed: N = 16384.
#define N_ELEM  16384
#define TN      256                         // tile dimension (rows=cols=threads)
#define NTILES  (N_ELEM / TN)               // 64
#define NBLOCKS (NTILES * (NTILES + 1) / 2) // 2080 upper-triangle tiles

typedef unsigned long long ull;

// Scratch for deterministic two-stage reduction (no cudaMalloc allowed).
__device__ float        g_partials[NBLOCKS];
__device__ unsigned int g_arrive = 0;       // reset to 0 by last block each launch

__device__ __forceinline__ float tanhf_mufu(float x) {
    float y; asm("tanh.approx.f32 %0, %1;" : "=f"(y) : "f"(x)); return y;
}
__device__ __forceinline__ ull pack2(float lo, float hi) {
    ull r; asm("mov.b64 %0, {%1, %2};" : "=l"(r) : "f"(lo), "f"(hi)); return r;
}
__device__ __forceinline__ void unpack2(float& lo, float& hi, ull v) {
    asm("mov.b64 {%0, %1}, %2;" : "=f"(lo), "=f"(hi) : "l"(v));
}
__device__ __forceinline__ ull add2(ull a, ull b) {
    ull r; asm("add.rn.f32x2 %0, %1, %2;" : "=l"(r) : "l"(a), "l"(b)); return r;
}
__device__ __forceinline__ ull mul2(ull a, ull b) {
    ull r; asm("mul.rn.f32x2 %0, %1, %2;" : "=l"(r) : "l"(a), "l"(b)); return r;
}
__device__ __forceinline__ ull fma2(ull a, ull b, ull c) {
    ull r; asm("fma.rn.f32x2 %0, %1, %2, %3;" : "=l"(r) : "l"(a), "l"(b), "l"(c)); return r;
}

// One block = one TN x TN tile (I,J) of the upper triangle (I <= J).
// sigmoid(z) = 0.5 + 0.5*tanh(z/2) =>
//   sum_tile sigmoid(p_i p_j)*|t_i - t_j| = 0.5*(A + B),
//   A = sum tanh(p_i * (p_j/2)) * |d|,  B = sum |d|.
// Diagonal tiles computed full and scaled 0.5 (diag itself contributes 0).
__global__ __launch_bounds__(TN) void pair_tile_kernel(
    const float* __restrict__ yt, const float* __restrict__ yp,
    float* __restrict__ out)
{
    // sh[m].x = packed (-t(2m), -t(2m+1)); sh[m].y = packed (p(2m)/2, p(2m+1)/2)
    __shared__ __align__(16) ulonglong2 sh[TN / 2];
    __shared__ float  red[TN / 32];
    __shared__ double dred[TN / 32];
    __shared__ unsigned int is_last;

    // Invert linear triangular block index k -> (I, J), I <= J.
    const int k = blockIdx.x;
    const float disc = 2.0f * (float)NTILES + 1.0f;
    int I = (int)((disc - sqrtf(disc * disc - 8.0f * (float)k)) * 0.5f);
    if (I < 0) I = 0;
    if (I >= NTILES) I = NTILES - 1;
    while (((I + 1) * NTILES - ((I + 1) * I) / 2) <= k) ++I;
    while ((I * NTILES - (I * (I - 1)) / 2) > k) --I;
    const int J = I + (k - (I * NTILES - (I * (I - 1)) / 2));

    const int tid  = threadIdx.x;
    const int lane = tid & 31;
    const int wid  = tid >> 5;

    // Stage column tile (interleaved packed layout for LDS.128 broadcast reads).
    {
        const int jg = J * TN + tid;
        const float tj = yt[jg];
        const float pj = yp[jg];
        float* sf = (float*)sh;
        const int m = tid >> 1, l = tid & 1;
        sf[4 * m + l]     = -tj;
        sf[4 * m + 2 + l] = 0.5f * pj;
    }

    // This thread's row.
    const int ig = I * TN + tid;
    const float pi = yp[ig];
    const float ti = yt[ig];
    const ull tip = pack2(ti, ti);
    const ull pip = pack2(pi, pi);
    __syncthreads();

    // Packed accumulators: A (tanh-weighted), B (plain |d|), 2 chains each.
    ull A0 = 0ull, A1 = 0ull, B0 = 0ull, B1 = 0ull;
    #pragma unroll 8
    for (int m = 0; m < TN / 2; m += 2) {
        const ulonglong2 v0 = sh[m];
        const ulonglong2 v1 = sh[m + 1];
        const ull d0  = add2(tip, v0.x);                  // (ti - t, ti - t')
        const ull d1  = add2(tip, v1.x);
        const ull ad0 = d0 & 0x7FFFFFFF7FFFFFFFull;       // |d| both lanes (ALU)
        const ull ad1 = d1 & 0x7FFFFFFF7FFFFFFFull;
        const ull x0  = mul2(pip, v0.y);                  // pi * p_j/2
        const ull x1  = mul2(pip, v1.y);
        float xa, xb, xc, xd;
        unpack2(xa, xb, x0);
        unpack2(xc, xd, x1);
        const ull th0 = pack2(tanhf_mufu(xa), tanhf_mufu(xb));
        const ull th1 = pack2(tanhf_mufu(xc), tanhf_mufu(xd));
        A0 = fma2(th0, ad0, A0);
        A1 = fma2(th1, ad1, A1);
        B0 = add2(B0, ad0);
        B1 = add2(B1, ad1);
    }

    float a0l, a0h, a1l, a1h, b0l, b0h, b1l, b1h;
    unpack2(a0l, a0h, A0); unpack2(a1l, a1h, A1);
    unpack2(b0l, b0h, B0); unpack2(b1l, b1h, B1);
    float P = 0.5f * (((a0l + a0h) + (a1l + a1h)) + ((b0l + b0h) + (b1l + b1h)));
    if (I == J) P *= 0.5f;

    // Warp shuffle reduction, then one shared stage over warp leaders.
    #pragma unroll
    for (int o = 16; o > 0; o >>= 1)
        P += __shfl_xor_sync(0xFFFFFFFFu, P, o);
    if (lane == 0) red[wid] = P;
    __syncthreads();

    // Publish partial; last-arriving block does the (deterministic) final sum.
    if (tid == 0) {
        float s = 0.f;
        #pragma unroll
        for (int w = 0; w < TN / 32; w++) s += red[w];
        g_partials[k] = s;
        __threadfence();
        unsigned int old = atomicAdd(&g_arrive, 1u);
        is_last = (old == (unsigned)(NBLOCKS - 1)) ? 1u : 0u;
    }
    __syncthreads();

    if (is_last) {
        __threadfence();
        double s = 0.0;
        for (int i = tid; i < NBLOCKS; i += TN)  // fixed order -> deterministic
            s += (double)g_partials[i];
        #pragma unroll
        for (int o = 16; o > 0; o >>= 1)
            s += __shfl_xor_sync(0xFFFFFFFFu, s, o);
        if (lane == 0) dred[wid] = s;
        __syncthreads();
        if (tid == 0) {
            double tot = 0.0;
            #pragma unroll
            for (int w = 0; w < TN / 32; w++) tot += dred[w];
            const double n2 = (double)N_ELEM * (double)N_ELEM;
            out[0] = (float)(-tot / n2);
            g_arrive = 0;  // re-arm for next graph replay
        }
    }
}

extern "C" void kernel_launch(void* const* d_in, const int* in_sizes, int n_in,
                              void* d_out, int out_size)
{
    const float* yt = (const float*)d_in[0];  // y_true
    const float* yp = (const float*)d_in[1];  // y_pred
    float* out = (float*)d_out;

    pair_tile_kernel<<<NBLOCKS, TN>>>(yt, yp, out);
}